// round 2
// baseline (speedup 1.0000x reference)
#include <cuda_runtime.h>
#include <math.h>

#define Bb 64
#define Tt 4096
#define Ii 128
#define Hh 256
#define LCH 128
#define NC (Tt/LCH)   // 32
#define Mtot (Bb*Tt)  // 262144

// Scratch (device globals — allocation-free per harness rules)
__device__ float g_cur[(size_t)Bb*Tt*Hh];     // 256 MiB: [b][t][h]
__device__ float g_local[Bb*NC*Hh];
__device__ float g_init[Bb*NC*Hh];

__device__ __forceinline__ float sigmoidf_(float v) {
    return 1.0f / (1.0f + expf(-v));
}

// ---------------------------------------------------------------------------
// Kernel 1: cur[m][h] = x[m][:] . Wd[h][:] + bd[h]
// M=262144, N=256, K=128. Block tile 128x128, thread tile 8x8, BK=16.
// ---------------------------------------------------------------------------
#define BM 128
#define BN 128
#define BK 16

__global__ __launch_bounds__(256, 2)
void gemm_kernel(const float* __restrict__ x, const float* __restrict__ Wd,
                 const float* __restrict__ bd, float* __restrict__ cur) {
    __shared__ float As[BK][BM];  // [k][m]
    __shared__ float Bs[BK][BN];  // [k][n]
    const int bm = blockIdx.x;
    const int bn = blockIdx.y;          // 0..1
    const int tid = threadIdx.x;        // 0..255
    const int tx = tid & 15;            // n-tile
    const int ty = tid >> 4;            // m-tile

    const float* xblk = x  + (size_t)bm * BM * Ii;
    const float* wblk = Wd + (size_t)bn * BN * Ii;

    float acc[8][8];
    #pragma unroll
    for (int i = 0; i < 8; i++)
        #pragma unroll
        for (int j = 0; j < 8; j++) acc[i][j] = 0.0f;

    for (int k0 = 0; k0 < Ii; k0 += BK) {
        // Load A tile: 128 rows x 16 k, transposed into As[k][m]
        #pragma unroll
        for (int r = 0; r < 2; r++) {
            int idx = tid + r * 256;        // 0..511
            int row = idx >> 2;
            int kq  = (idx & 3) << 2;
            float4 v = *(const float4*)(xblk + (size_t)row * Ii + k0 + kq);
            As[kq + 0][row] = v.x; As[kq + 1][row] = v.y;
            As[kq + 2][row] = v.z; As[kq + 3][row] = v.w;
        }
        // Load B tile: 128 Wd rows (n) x 16 k into Bs[k][n]
        #pragma unroll
        for (int r = 0; r < 2; r++) {
            int idx = tid + r * 256;
            int row = idx >> 2;
            int kq  = (idx & 3) << 2;
            float4 v = *(const float4*)(wblk + (size_t)row * Ii + k0 + kq);
            Bs[kq + 0][row] = v.x; Bs[kq + 1][row] = v.y;
            Bs[kq + 2][row] = v.z; Bs[kq + 3][row] = v.w;
        }
        __syncthreads();

        #pragma unroll
        for (int kk = 0; kk < BK; kk++) {
            float a[8], b[8];
            #pragma unroll
            for (int i = 0; i < 4; i++) {
                a[i]     = As[kk][ty * 4 + i];
                a[i + 4] = As[kk][64 + ty * 4 + i];
            }
            #pragma unroll
            for (int j = 0; j < 4; j++) {
                b[j]     = Bs[kk][tx * 4 + j];
                b[j + 4] = Bs[kk][64 + tx * 4 + j];
            }
            #pragma unroll
            for (int i = 0; i < 8; i++)
                #pragma unroll
                for (int j = 0; j < 8; j++)
                    acc[i][j] = fmaf(a[i], b[j], acc[i][j]);
        }
        __syncthreads();
    }

    // Epilogue: add bias, store. Row/col mapping matches the split 4+4 tiles.
    #pragma unroll
    for (int ih = 0; ih < 2; ih++) {
        #pragma unroll
        for (int i = 0; i < 4; i++) {
            int row = bm * BM + ih * 64 + ty * 4 + i;
            #pragma unroll
            for (int jh = 0; jh < 2; jh++) {
                int col = bn * BN + jh * 64 + tx * 4;
                float4 o;
                o.x = acc[ih * 4 + i][jh * 4 + 0] + bd[col + 0];
                o.y = acc[ih * 4 + i][jh * 4 + 1] + bd[col + 1];
                o.z = acc[ih * 4 + i][jh * 4 + 2] + bd[col + 2];
                o.w = acc[ih * 4 + i][jh * 4 + 3] + bd[col + 3];
                *(float4*)(cur + (size_t)row * Hh + col) = o;
            }
        }
    }
}

// ---------------------------------------------------------------------------
// Kernel 2: per-(b,chunk) local scan from zero → g_local
// ---------------------------------------------------------------------------
__global__ __launch_bounds__(256)
void local_kernel(const float* __restrict__ tau) {
    const int b = blockIdx.x;
    const int ck = blockIdx.y;
    const int h = threadIdx.x;
    const float alpha = sigmoidf_(tau[h]);
    const float om = 1.0f - alpha;
    const float* c = g_cur + ((size_t)b * Tt + (size_t)ck * LCH) * Hh + h;
    float s = 0.0f;
    #pragma unroll 4
    for (int t = 0; t < LCH; t++) {
        s = fmaf(alpha, s, om * c[(size_t)t * Hh]);
    }
    g_local[(b * NC + ck) * Hh + h] = s;
}

// ---------------------------------------------------------------------------
// Kernel 3: sequential cross-chunk combine → g_init (state entering each chunk)
// ---------------------------------------------------------------------------
__global__ __launch_bounds__(256)
void combine_kernel(const float* __restrict__ tau) {
    const int b = blockIdx.x;
    const int h = threadIdx.x;
    const float alpha = sigmoidf_(tau[h]);
    const float aL = powf(alpha, (float)LCH);
    float s = 0.0f;
    #pragma unroll
    for (int k = 0; k < NC; k++) {
        g_init[(b * NC + k) * Hh + h] = s;
        s = fmaf(aL, s, g_local[(b * NC + k) * Hh + h]);
    }
}

// ---------------------------------------------------------------------------
// Kernel 4: scan with correct initial state, fused Wo-dot + sigmoid epilogue
// ---------------------------------------------------------------------------
__global__ __launch_bounds__(256)
void out_kernel(const float* __restrict__ tau, const float* __restrict__ Wo,
                const float* __restrict__ bo, float* __restrict__ out) {
    const int b = blockIdx.x;
    const int ck = blockIdx.y;
    const int h = threadIdx.x;
    const int warp = h >> 5;
    const int lane = h & 31;
    __shared__ float part[LCH][9];  // pad to 9 → conflict-free reduce reads

    const float alpha = sigmoidf_(tau[h]);
    const float om = 1.0f - alpha;
    const float w = Wo[h];
    float s = g_init[(b * NC + ck) * Hh + h];
    const float* c = g_cur + ((size_t)b * Tt + (size_t)ck * LCH) * Hh + h;

    #pragma unroll 4
    for (int t = 0; t < LCH; t++) {
        s = fmaf(alpha, s, om * c[(size_t)t * Hh]);
        float p = w * s;
        #pragma unroll
        for (int o = 16; o; o >>= 1) p += __shfl_xor_sync(0xFFFFFFFFu, p, o);
        if (lane == 0) part[t][warp] = p;
    }
    __syncthreads();

    if (h < LCH) {
        float v = bo[0];
        #pragma unroll
        for (int wi = 0; wi < 8; wi++) v += part[h][wi];
        out[(size_t)b * Tt + (size_t)ck * LCH + h] = sigmoidf_(v);
    }
}

// ---------------------------------------------------------------------------
extern "C" void kernel_launch(void* const* d_in, const int* in_sizes, int n_in,
                              void* d_out, int out_size) {
    const float* x   = (const float*)d_in[0];
    const float* Wd  = (const float*)d_in[1];
    const float* bd  = (const float*)d_in[2];
    const float* Wo  = (const float*)d_in[3];
    const float* bo  = (const float*)d_in[4];
    const float* tau = (const float*)d_in[5];
    float* out = (float*)d_out;

    float* cur;
    cudaGetSymbolAddress((void**)&cur, g_cur);

    dim3 ggrid(Mtot / BM, Hh / BN);
    gemm_kernel<<<ggrid, 256>>>(x, Wd, bd, cur);

    dim3 sgrid(Bb, NC);
    local_kernel<<<sgrid, Hh>>>(tau);
    combine_kernel<<<Bb, Hh>>>(tau);
    out_kernel<<<sgrid, Hh>>>(tau, Wo, bo, out);
}

// round 7
// speedup vs baseline: 1.6898x; 1.6898x over previous
#include <cuda_runtime.h>
#include <cstdint>
#include <math.h>

typedef unsigned int u32;

#define Bb 64
#define Tt 4096
#define Ii 128
#define Hh 256
#define LCH 64
#define NC (Tt/LCH)       // 64 chunks of 64
#define CURS 132          // cur tile smem row stride (floats)
#define ABS 12            // A/B chunk smem row stride (b32)
#define PS 257            // k3 power-table stride

// Scratch (device globals — allocation-free)
__device__ float g_local[(size_t)Bb*NC*Hh];      // 4 MB
__device__ float g_init [(size_t)Bb*NC*Hh];      // 4 MB
__device__ float g_dpart[(size_t)Bb*Tt*2];       // 2 MB: [b][t][hhalf]

__device__ __forceinline__ float sigmoidf_(float v) {
    return 1.0f / (1.0f + expf(-v));
}
__device__ __forceinline__ u32 f2tf(float f) {
    u32 u; asm("cvt.rna.tf32.f32 %0, %1;" : "=r"(u) : "f"(f)); return u;
}

// ---------------------------------------------------------------------------
// K1: per (t-tile 128, b, h-half 128):
//   tf32 tensor-core GEMM cur = x·Wd^T + bd  (tile in smem)
//   -> local scan (2 sub-chunks of 64, parallel) -> g_local
//   -> per-t partial dot with Wo -> g_dpart
// Smem: curS[128][132] | A[2][128][12] | B[2][128][12] | wo[128] | bd[128]
// ---------------------------------------------------------------------------
#define SM_CUR 0
#define SM_A   16896
#define SM_B   19968
#define SM_WO  23040
#define SM_BD  23168
#define SM1_BYTES ((23168+128)*4)   // 93184

__global__ __launch_bounds__(256, 2)
void k1_gemm_scan(const float* __restrict__ x, const float* __restrict__ Wd,
                  const float* __restrict__ bd, const float* __restrict__ Wo,
                  const float* __restrict__ tau) {
    extern __shared__ float sm[];
    float* curS = sm + SM_CUR;
    u32*   As   = (u32*)(sm + SM_A);
    u32*   Bs   = (u32*)(sm + SM_B);
    float* woS  = sm + SM_WO;
    float* bdS  = sm + SM_BD;

    const int tchunk = blockIdx.x >> 1;     // 0..31 (128-t tile)
    const int hh     = blockIdx.x & 1;      // h-half
    const int b      = blockIdx.y;
    const int tid  = threadIdx.x;
    const int wid  = tid >> 5, lane = tid & 31;
    const int warp_m = wid >> 1, warp_n = wid & 1;
    const int gr = lane >> 2, tg = lane & 3;

    const float* xblk = x  + ((size_t)b * Tt + (size_t)tchunk * 128) * Ii;
    const float* wblk = Wd + (size_t)hh * 128 * Ii;

    if (tid < 128) {
        woS[tid] = Wo[hh * 128 + tid];
        bdS[tid] = bd[hh * 128 + tid];
    }

    const int lrow = tid >> 1;          // 0..127
    const int lko  = (tid & 1) * 4;     // 0 or 4

    // preload k-chunk 0 into buffer 0
    float4 av = *(const float4*)(xblk + (size_t)lrow * Ii + lko);
    float4 bv = *(const float4*)(wblk + (size_t)lrow * Ii + lko);
    {
        u32* ap = As + lrow * ABS + lko;
        ap[0]=f2tf(av.x); ap[1]=f2tf(av.y); ap[2]=f2tf(av.z); ap[3]=f2tf(av.w);
        u32* bp = Bs + lrow * ABS + lko;
        bp[0]=f2tf(bv.x); bp[1]=f2tf(bv.y); bp[2]=f2tf(bv.z); bp[3]=f2tf(bv.w);
    }
    __syncthreads();

    float acc[2][8][4];
    #pragma unroll
    for (int mi=0;mi<2;mi++)
        #pragma unroll
        for (int ni=0;ni<8;ni++)
            #pragma unroll
            for (int q=0;q<4;q++) acc[mi][ni][q] = 0.0f;

    for (int kc = 0; kc < 16; kc++) {
        const int bufo = (kc & 1) * 128 * ABS;
        if (kc < 15) {
            av = *(const float4*)(xblk + (size_t)lrow * Ii + (kc+1)*8 + lko);
            bv = *(const float4*)(wblk + (size_t)lrow * Ii + (kc+1)*8 + lko);
        }
        u32 bf[8][2];
        #pragma unroll
        for (int ni = 0; ni < 8; ni++) {
            const int n = warp_n * 64 + ni * 8 + gr;
            bf[ni][0] = Bs[bufo + n * ABS + tg];
            bf[ni][1] = Bs[bufo + n * ABS + tg + 4];
        }
        #pragma unroll
        for (int mi = 0; mi < 2; mi++) {
            const int r = warp_m * 32 + mi * 16 + gr;
            u32 a0 = As[bufo + r * ABS + tg];
            u32 a1 = As[bufo + (r + 8) * ABS + tg];
            u32 a2 = As[bufo + r * ABS + tg + 4];
            u32 a3 = As[bufo + (r + 8) * ABS + tg + 4];
            #pragma unroll
            for (int ni = 0; ni < 8; ni++) {
                asm volatile(
                  "mma.sync.aligned.m16n8k8.row.col.f32.tf32.tf32.f32 "
                  "{%0,%1,%2,%3}, {%4,%5,%6,%7}, {%8,%9}, {%0,%1,%2,%3};"
                  : "+f"(acc[mi][ni][0]), "+f"(acc[mi][ni][1]),
                    "+f"(acc[mi][ni][2]), "+f"(acc[mi][ni][3])
                  : "r"(a0), "r"(a1), "r"(a2), "r"(a3),
                    "r"(bf[ni][0]), "r"(bf[ni][1]));
            }
        }
        if (kc < 15) {
            const int nbo = ((kc + 1) & 1) * 128 * ABS;
            u32* ap = As + nbo + lrow * ABS + lko;
            ap[0]=f2tf(av.x); ap[1]=f2tf(av.y); ap[2]=f2tf(av.z); ap[3]=f2tf(av.w);
            u32* bp = Bs + nbo + lrow * ABS + lko;
            bp[0]=f2tf(bv.x); bp[1]=f2tf(bv.y); bp[2]=f2tf(bv.z); bp[3]=f2tf(bv.w);
        }
        __syncthreads();
    }

    // epilogue: acc + bias -> curS[t][h]
    #pragma unroll
    for (int mi = 0; mi < 2; mi++) {
        #pragma unroll
        for (int ni = 0; ni < 8; ni++) {
            const int r = warp_m * 32 + mi * 16 + gr;
            const int c = warp_n * 64 + ni * 8 + 2 * tg;
            curS[r * CURS + c]           = acc[mi][ni][0] + bdS[c];
            curS[r * CURS + c + 1]       = acc[mi][ni][1] + bdS[c + 1];
            curS[(r + 8) * CURS + c]     = acc[mi][ni][2] + bdS[c];
            curS[(r + 8) * CURS + c + 1] = acc[mi][ni][3] + bdS[c + 1];
        }
    }
    __syncthreads();

    // local scan: thread = (h, sub-chunk of 64); overwrite curS with localmem
    {
        const int h  = tid & 127;
        const int sc = tid >> 7;
        const int hg = hh * 128 + h;
        const float alpha = sigmoidf_(tau[hg]);
        const float om = 1.0f - alpha;
        float s = 0.0f;
        const int tbase = sc * 64;
        #pragma unroll 8
        for (int j = 0; j < 64; j++) {
            float v = curS[(tbase + j) * CURS + h];
            s = fmaf(alpha, s, om * v);
            curS[(tbase + j) * CURS + h] = s;
        }
        g_local[((size_t)b * NC + tchunk * 2 + sc) * Hh + hg] = s;
    }
    __syncthreads();

    // per-t partial dot with Wo over this h-half
    {
        const int t = tid >> 1, seg = tid & 1;
        float p = 0.0f;
        #pragma unroll 8
        for (int j = 0; j < 64; j++) {
            const int c = seg * 64 + j;
            p = fmaf(curS[t * CURS + c], woS[c], p);
        }
        p += __shfl_down_sync(0xFFFFFFFFu, p, 1);
        if (seg == 0)
            g_dpart[((size_t)b * Tt + tchunk * 128 + t) * 2 + hh] = p;
    }
}

// ---------------------------------------------------------------------------
// K2: sequential cross-chunk combine -> g_init (state entering each chunk)
// ---------------------------------------------------------------------------
__global__ __launch_bounds__(256)
void k2_combine(const float* __restrict__ tau) {
    const int b = blockIdx.x;
    const int h = threadIdx.x;
    const float alpha = sigmoidf_(tau[h]);
    const float aL = exp2f(64.0f * log2f(alpha));
    float s = 0.0f;
    #pragma unroll
    for (int k = 0; k < NC; k++) {
        const size_t idx = ((size_t)b * NC + k) * Hh + h;
        g_init[idx] = s;
        s = fmaf(aL, s, g_local[idx]);
    }
}

// ---------------------------------------------------------------------------
// K3: out = sigmoid(d_loc + corr_t + bo), corr_t = sum_h Wo[h]*alpha^{t+1}*init[h]
// via smem power table pw[t][h] = alpha^{t+1} * Wo[h] * init[h]
// ---------------------------------------------------------------------------
#define SM3_BYTES (64 * PS * 4)   // 65792

__global__ __launch_bounds__(256)
void k3_out(const float* __restrict__ tau, const float* __restrict__ Wo,
            const float* __restrict__ bo, float* __restrict__ out) {
    extern __shared__ float pw[];
    const int ch = blockIdx.x;
    const int b  = blockIdx.y;
    const int tid = threadIdx.x;

    {   // build table: thread = h
        const int h = tid;
        const float alpha = sigmoidf_(tau[h]);
        float p = alpha * Wo[h] * g_init[((size_t)b * NC + ch) * Hh + h];
        #pragma unroll 8
        for (int t = 0; t < 64; t++) { pw[t * PS + h] = p; p *= alpha; }
    }
    __syncthreads();

    {   // reduce: 4 threads per t, 64 h each
        const int t = tid >> 2, q = tid & 3;
        float a = 0.0f;
        #pragma unroll 8
        for (int j = 0; j < 64; j++) a += pw[t * PS + q * 64 + j];
        a += __shfl_xor_sync(0xFFFFFFFFu, a, 1);
        a += __shfl_xor_sync(0xFFFFFFFFu, a, 2);
        if (q == 0) {
            const size_t tg = (size_t)b * Tt + ch * 64 + t;
            const float2 dp = *(const float2*)(g_dpart + tg * 2);
            out[tg] = sigmoidf_(dp.x + dp.y + a + bo[0]);
        }
    }
}

// ---------------------------------------------------------------------------
extern "C" void kernel_launch(void* const* d_in, const int* in_sizes, int n_in,
                              void* d_out, int out_size) {
    const float* x   = (const float*)d_in[0];
    const float* Wd  = (const float*)d_in[1];
    const float* bd  = (const float*)d_in[2];
    const float* Wo  = (const float*)d_in[3];
    const float* bo  = (const float*)d_in[4];
    const float* tau = (const float*)d_in[5];
    float* out = (float*)d_out;

    cudaFuncSetAttribute(k1_gemm_scan,
        cudaFuncAttributeMaxDynamicSharedMemorySize, SM1_BYTES);
    cudaFuncSetAttribute(k3_out,
        cudaFuncAttributeMaxDynamicSharedMemorySize, SM3_BYTES);

    dim3 g1(64, Bb);               // x: (tchunk<<1)|hh, y: b
    k1_gemm_scan<<<g1, 256, SM1_BYTES>>>(x, Wd, bd, Wo, tau);

    k2_combine<<<Bb, Hh>>>(tau);

    dim3 g3(NC, Bb);
    k3_out<<<g3, 256, SM3_BYTES>>>(tau, Wo, bo, out);
}